// round 3
// baseline (speedup 1.0000x reference)
#include <cuda_runtime.h>

#define NF   32
#define NDOF 29
#define BLK  128          // 32 batches per block, 4 lanes per batch (one per pose row)

// ---------------------------------------------------------------------------
// Fast sincos: Cody-Waite reduction + short polys. All FMA-pipe, no MUFU.
// ---------------------------------------------------------------------------
__device__ __forceinline__ void fast_sincos(float a, float &s, float &c) {
    float q  = rintf(a * 0.63661977236758134f);   // a * 2/pi
    int   iq = (int)q;
    float r  = fmaf(q, -1.5707962513e+0f, a);
    r        = fmaf(q, -7.5497894159e-8f, r);
    float r2 = r * r;

    float ps = fmaf(r2, -1.9841270e-4f, 8.3333333e-3f);
    ps       = fmaf(r2, ps, -1.6666667e-1f);
    float sr = fmaf(r * r2, ps, r);

    float pc = fmaf(r2, -1.3888889e-3f, 4.1666668e-2f);
    pc       = fmaf(r2, pc, -5.0e-1f);
    float cr = fmaf(r2, pc, 1.0f);

    bool  sw = (iq & 1);
    float ss = sw ? cr : sr;
    float cc = sw ? sr : cr;
    unsigned sgn_s = ((unsigned)(iq & 2)) << 30;
    unsigned sgn_c = ((unsigned)((iq + 1) & 2)) << 30;
    s = __uint_as_float(__float_as_uint(ss) ^ sgn_s);
    c = __uint_as_float(__float_as_uint(cc) ^ sgn_c);
}

__global__ void __launch_bounds__(BLK, 10)
fk_kernel(const float* __restrict__ ja,        // [B, 29]
          const float* __restrict__ axes,      // [32, 3]
          const float* __restrict__ origins,   // [32, 4, 4]
          const float* __restrict__ mmult,     // [2]
          const float* __restrict__ moff,      // [2]
          const int*   __restrict__ ctrl,      // [29]
          const int*   __restrict__ msrc,      // [2]
          const int*   __restrict__ mdst,      // [2]
          const int*   __restrict__ types,     // [32]
          float*       __restrict__ out,       // [B, 32, 4, 4]
          int Bn)
{
    // Per (frame,row) constants, 3 x float4 each:
    //   c0 = (A0.xyz = O_r.xyz,            O_r.w)
    //   c1 = (A1.xyz = O_r x k  [rev only], v_eff = O_r.k [prismatic only])
    //   c2 = (A2.xyz = (O_r.k)k - O_r.xyz [rev only], 0)
    // L_row = c0.xyz + sn*c1.xyz + (1-cs)*c2.xyz ;  L_row.w = a*c1.w + c0.w
    __shared__ __align__(16) float4 s_cst[NF * 4 * 3];   // 6 KB
    __shared__ float s_ang[NF * 32];                     // final angle per (frame, batch)
    __shared__ float s_raw[32 * NDOF];                   // raw joint angles for this block
    __shared__ int   s_slot[NF];
    __shared__ int   s_mslot[NF];
    __shared__ float s_mm[NF], s_mo[NF];

    const int tid  = threadIdx.x;
    const int r    = tid & 3;        // pose row owned by this lane
    const int bt   = tid >> 2;       // batch within block (0..31)
    const int b0   = blockIdx.x * 32;
    const int gbat = b0 + bt;

    // ---- per-frame meta (ctrl slot / mimic resolution) ----
    if (tid < NF) {
        const int f = tid;
        int slot = -1;
        for (int j = 0; j < NDOF; ++j) if (ctrl[j] == f) slot = j;
        s_slot[f] = slot;
        int ms = -1; float mm = 0.f, mo = 0.f;
        for (int m = 0; m < 2; ++m) {
            if (mdst[m] == f) {
                const int sf = msrc[m];
                for (int j = 0; j < NDOF; ++j) if (ctrl[j] == sf) ms = j;
                mm = mmult[m]; mo = moff[m];
            }
        }
        s_mslot[f] = ms; s_mm[f] = mm; s_mo[f] = mo;
    }

    // ---- per (frame,row) constants: exactly 128 threads = 32 frames x 4 rows ----
    {
        const int f  = tid >> 2;
        const int rr = tid & 3;
        const float4 orow = *reinterpret_cast<const float4*>(origins + f * 16 + rr * 4);
        const float kx = axes[f * 3 + 0], ky = axes[f * 3 + 1], kz = axes[f * 3 + 2];
        const int   ty = types[f];
        const float vr = orow.x * kx + orow.y * ky + orow.z * kz;
        float a1x = 0.f, a1y = 0.f, a1z = 0.f;
        float a2x = 0.f, a2y = 0.f, a2z = 0.f;
        float ve  = 0.f;
        if (ty == 1) {                       // revolute
            a1x = orow.y * kz - orow.z * ky; // O_r x k
            a1y = orow.z * kx - orow.x * kz;
            a1z = orow.x * ky - orow.y * kx;
            a2x = fmaf(vr, kx, -orow.x);     // (O_r.k)k - O_r
            a2y = fmaf(vr, ky, -orow.y);
            a2z = fmaf(vr, kz, -orow.z);
        } else if (ty == 2) {                // prismatic
            ve = vr;
        }
        s_cst[tid * 3 + 0] = make_float4(orow.x, orow.y, orow.z, orow.w);
        s_cst[tid * 3 + 1] = make_float4(a1x, a1y, a1z, ve);
        s_cst[tid * 3 + 2] = make_float4(a2x, a2y, a2z, 0.f);
    }

    // ---- stage raw joint angles (coalesced) ----
    for (int i = tid; i < 32 * NDOF; i += BLK) {
        const int bb = i / NDOF;
        s_raw[i] = (b0 + bb < Bn) ? ja[(size_t)b0 * NDOF + i] : 0.f;
    }
    __syncthreads();

    // ---- resolve final per-(frame,batch) angles ----
    for (int i = tid; i < NF * 32; i += BLK) {
        const int f  = i >> 5;
        const int bb = i & 31;
        const int sl = s_slot[f];
        float a;
        if (sl >= 0) a = s_raw[bb * NDOF + sl];
        else {
            const int ms = s_mslot[f];
            a = (ms >= 0) ? fmaf(s_raw[bb * NDOF + ms], s_mm[f], s_mo[f]) : 0.f;
        }
        s_ang[i] = a;
    }
    __syncthreads();

    // ---- main chain: branch-free, sync-free, direct stores ----
    float p0 = (r == 0) ? 1.f : 0.f;
    float p1 = (r == 1) ? 1.f : 0.f;
    float p2 = (r == 2) ? 1.f : 0.f;
    float p3 = (r == 3) ? 1.f : 0.f;
    float q0 = 0.f, q1 = 0.f, q2 = 0.f, q3 = 0.f;   // saved pose of frame 10

    float4* const out4  = reinterpret_cast<float4*>(out);
    const size_t  obase = (size_t)gbat * NF * 4 + r;
    const float4* cp    = s_cst + r * 3;
    const float*  ap    = s_ang + bt;
    const bool    ok    = (gbat < Bn);

    #pragma unroll
    for (int f = 0; f < NF; ++f) {
        if (f == 30 || f == 31) { p0 = q0; p1 = q1; p2 = q2; p3 = q3; }

        const float a = ap[f * 32];
        float sn, cs;
        fast_sincos(a, sn, cs);
        const float C = 1.f - cs;

        const float4 c0 = cp[f * 12 + 0];
        const float4 c1 = cp[f * 12 + 1];
        const float4 c2 = cp[f * 12 + 2];
        const float l0 = fmaf(C, c2.x, fmaf(sn, c1.x, c0.x));
        const float l1 = fmaf(C, c2.y, fmaf(sn, c1.y, c0.y));
        const float l2 = fmaf(C, c2.z, fmaf(sn, c1.z, c0.z));
        const float l3 = fmaf(a, c1.w, c0.w);

        // share L rows 0..2 within the 4-lane group
        const float A0 = __shfl_sync(0xffffffffu, l0, 0, 4);
        const float A1 = __shfl_sync(0xffffffffu, l1, 0, 4);
        const float A2 = __shfl_sync(0xffffffffu, l2, 0, 4);
        const float A3 = __shfl_sync(0xffffffffu, l3, 0, 4);
        const float B0 = __shfl_sync(0xffffffffu, l0, 1, 4);
        const float B1 = __shfl_sync(0xffffffffu, l1, 1, 4);
        const float B2 = __shfl_sync(0xffffffffu, l2, 1, 4);
        const float B3 = __shfl_sync(0xffffffffu, l3, 1, 4);
        const float D0 = __shfl_sync(0xffffffffu, l0, 2, 4);
        const float D1 = __shfl_sync(0xffffffffu, l1, 2, 4);
        const float D2 = __shfl_sync(0xffffffffu, l2, 2, 4);
        const float D3 = __shfl_sync(0xffffffffu, l3, 2, 4);

        // P_row = P_row @ L   (L row 3 = (0,0,0,1) by construction)
        const float n0 = fmaf(p0, A0, fmaf(p1, B0, p2 * D0));
        const float n1 = fmaf(p0, A1, fmaf(p1, B1, p2 * D1));
        const float n2 = fmaf(p0, A2, fmaf(p1, B2, p2 * D2));
        const float n3 = fmaf(p0, A3, fmaf(p1, B3, fmaf(p2, D3, p3)));
        p0 = n0; p1 = n1; p2 = n2; p3 = n3;

        if (f == 10) { q0 = p0; q1 = p1; q2 = p2; q3 = p3; }

        if (ok) out4[obase + f * 4] = make_float4(p0, p1, p2, p3);
    }
}

extern "C" void kernel_launch(void* const* d_in, const int* in_sizes, int n_in,
                              void* d_out, int out_size) {
    const float* ja      = (const float*)d_in[0];
    const float* axes    = (const float*)d_in[1];
    const float* origins = (const float*)d_in[2];
    const float* mm      = (const float*)d_in[3];
    const float* mo      = (const float*)d_in[4];
    const int*   ctrl    = (const int*)d_in[5];
    const int*   msrc    = (const int*)d_in[6];
    const int*   mdst    = (const int*)d_in[7];
    const int*   types   = (const int*)d_in[8];
    float*       out     = (float*)d_out;

    const int Bn   = in_sizes[0] / NDOF;
    const int grid = (Bn + 31) / 32;          // 32 batches per block
    fk_kernel<<<grid, BLK>>>(ja, axes, origins, mm, mo, ctrl, msrc, mdst, types, out, Bn);
}

// round 4
// speedup vs baseline: 1.0382x; 1.0382x over previous
#include <cuda_runtime.h>

#define NF   32
#define NDOF 29
#define BLK  128          // 32 batches per block, 4 lanes per batch (one per pose row)

// ---------------------------------------------------------------------------
// Fast sincos: Cody-Waite reduction + short polys. All FMA-pipe, no MUFU.
// ---------------------------------------------------------------------------
__device__ __forceinline__ void fast_sincos(float a, float &s, float &c) {
    float q  = rintf(a * 0.63661977236758134f);   // a * 2/pi
    int   iq = (int)q;
    float r  = fmaf(q, -1.5707962513e+0f, a);
    r        = fmaf(q, -7.5497894159e-8f, r);
    float r2 = r * r;

    float ps = fmaf(r2, -1.9841270e-4f, 8.3333333e-3f);
    ps       = fmaf(r2, ps, -1.6666667e-1f);
    float sr = fmaf(r * r2, ps, r);

    float pc = fmaf(r2, -1.3888889e-3f, 4.1666668e-2f);
    pc       = fmaf(r2, pc, -5.0e-1f);
    float cr = fmaf(r2, pc, 1.0f);

    bool  sw = (iq & 1);
    float ss = sw ? cr : sr;
    float cc = sw ? sr : cr;
    unsigned sgn_s = ((unsigned)(iq & 2)) << 30;
    unsigned sgn_c = ((unsigned)((iq + 1) & 2)) << 30;
    s = __uint_as_float(__float_as_uint(ss) ^ sgn_s);
    c = __uint_as_float(__float_as_uint(cc) ^ sgn_c);
}

__global__ void __launch_bounds__(BLK, 10)
fk_kernel(const float* __restrict__ ja,        // [B, 29]
          const float* __restrict__ axes,      // [32, 3]
          const float* __restrict__ origins,   // [32, 4, 4]
          const float* __restrict__ mmult,     // [2]
          const float* __restrict__ moff,      // [2]
          const int*   __restrict__ ctrl,      // [29]
          const int*   __restrict__ msrc,      // [2]
          const int*   __restrict__ mdst,      // [2]
          const int*   __restrict__ types,     // [32]
          float*       __restrict__ out,       // [B, 32, 4, 4]
          int Bn)
{
    // Per (frame, row j in 0..2) constants, 3 x float4 each:
    //   cA = (O_j.xyz, O_j.w)
    //   cB = (O_j x k  [revolute only], O_j.k [prismatic only])
    //   cC = ((O_j.k)k - O_j.xyz [revolute only], 0)
    // L_j.xyz = cA + sn*cB + (1-cs)*cC ;  L_j.w = a*cB.w + cA.w
    __shared__ __align__(16) float4 s_cst[NF * 9];   // 4.5 KB
    __shared__ float s_ang[NF * 32];                 // final angle per (frame, batch)
    __shared__ float s_raw[32 * NDOF];
    __shared__ int   s_slot[NF];
    __shared__ int   s_mslot[NF];
    __shared__ float s_mm[NF], s_mo[NF];

    const int tid  = threadIdx.x;
    const int r    = tid & 3;        // pose row owned by this lane
    const int bt   = tid >> 2;       // batch within block (0..31)
    const int b0   = blockIdx.x * 32;
    const int gbat = b0 + bt;

    // ---- per-frame meta (ctrl slot / mimic resolution) ----
    if (tid < NF) {
        const int f = tid;
        int slot = -1;
        for (int j = 0; j < NDOF; ++j) if (ctrl[j] == f) slot = j;
        s_slot[f] = slot;
        int ms = -1; float mm = 0.f, mo = 0.f;
        for (int m = 0; m < 2; ++m) {
            if (mdst[m] == f) {
                const int sf = msrc[m];
                for (int j = 0; j < NDOF; ++j) if (ctrl[j] == sf) ms = j;
                mm = mmult[m]; mo = moff[m];
            }
        }
        s_mslot[f] = ms; s_mm[f] = mm; s_mo[f] = mo;
    }

    // ---- per (frame, row 0..2) constants: 96 pairs ----
    if (tid < NF * 3) {
        const int f  = tid / 3;
        const int rr = tid - f * 3;
        const float4 orow = *reinterpret_cast<const float4*>(origins + f * 16 + rr * 4);
        const float kx = axes[f * 3 + 0], ky = axes[f * 3 + 1], kz = axes[f * 3 + 2];
        const int   ty = types[f];
        const float vr = orow.x * kx + orow.y * ky + orow.z * kz;
        float bxx = 0.f, bxy = 0.f, bxz = 0.f;
        float cxx = 0.f, cxy = 0.f, cxz = 0.f;
        float ve  = 0.f;
        if (ty == 1) {                        // revolute
            bxx = orow.y * kz - orow.z * ky;  // O_j x k
            bxy = orow.z * kx - orow.x * kz;
            bxz = orow.x * ky - orow.y * kx;
            cxx = fmaf(vr, kx, -orow.x);      // (O_j.k)k - O_j
            cxy = fmaf(vr, ky, -orow.y);
            cxz = fmaf(vr, kz, -orow.z);
        } else if (ty == 2) {                 // prismatic
            ve = vr;
        }
        s_cst[(f * 3 + rr) * 3 + 0] = make_float4(orow.x, orow.y, orow.z, orow.w);
        s_cst[(f * 3 + rr) * 3 + 1] = make_float4(bxx, bxy, bxz, ve);
        s_cst[(f * 3 + rr) * 3 + 2] = make_float4(cxx, cxy, cxz, 0.f);
    }

    // ---- stage raw joint angles (coalesced) ----
    for (int i = tid; i < 32 * NDOF; i += BLK) {
        const int bb = i / NDOF;
        s_raw[i] = (b0 + bb < Bn) ? ja[(size_t)b0 * NDOF + i] : 0.f;
    }
    __syncthreads();

    // ---- resolve final per-(frame,batch) angles ----
    for (int i = tid; i < NF * 32; i += BLK) {
        const int f  = i >> 5;
        const int bb = i & 31;
        const int sl = s_slot[f];
        float a;
        if (sl >= 0) a = s_raw[bb * NDOF + sl];
        else {
            const int ms = s_mslot[f];
            a = (ms >= 0) ? fmaf(s_raw[bb * NDOF + ms], s_mm[f], s_mo[f]) : 0.f;
        }
        s_ang[i] = a;
    }
    __syncthreads();

    // ---- main chain: no shuffles, no syncs; every lane builds full L ----
    float p0 = (r == 0) ? 1.f : 0.f;
    float p1 = (r == 1) ? 1.f : 0.f;
    float p2 = (r == 2) ? 1.f : 0.f;
    float p3 = (r == 3) ? 1.f : 0.f;
    float q0 = 0.f, q1 = 0.f, q2 = 0.f, q3 = 0.f;   // this lane's row of pose-10

    float4* const op = reinterpret_cast<float4*>(out) + (size_t)gbat * (NF * 4) + r;
    const float*  ap = s_ang + bt;
    const bool    ok = (gbat < Bn);

    #pragma unroll 4
    for (int f = 0; f < NF; ++f) {
        if (f >= 30) { p0 = q0; p1 = q1; p2 = q2; p3 = q3; }

        const float a = ap[f * 32];
        float sn, cs;
        fast_sincos(a, sn, cs);
        const float C = 1.f - cs;

        const float4* cf = s_cst + f * 9;
        // build full local transform L (rows 0..2; row 3 = 0001 implicit)
        float L[12];
        #pragma unroll
        for (int j = 0; j < 3; ++j) {
            const float4 cA = cf[j * 3 + 0];
            const float4 cB = cf[j * 3 + 1];
            const float4 cC = cf[j * 3 + 2];
            L[j * 4 + 0] = fmaf(C, cC.x, fmaf(sn, cB.x, cA.x));
            L[j * 4 + 1] = fmaf(C, cC.y, fmaf(sn, cB.y, cA.y));
            L[j * 4 + 2] = fmaf(C, cC.z, fmaf(sn, cB.z, cA.z));
            L[j * 4 + 3] = fmaf(a, cB.w, cA.w);
        }

        // this lane's pose row update: P_r = P_r @ L
        const float n0 = fmaf(p0, L[0], fmaf(p1, L[4], p2 * L[8]));
        const float n1 = fmaf(p0, L[1], fmaf(p1, L[5], p2 * L[9]));
        const float n2 = fmaf(p0, L[2], fmaf(p1, L[6], p2 * L[10]));
        const float n3 = fmaf(p0, L[3], fmaf(p1, L[7], fmaf(p2, L[11], p3)));
        p0 = n0; p1 = n1; p2 = n2; p3 = n3;

        if (f == 10) { q0 = p0; q1 = p1; q2 = p2; q3 = p3; }

        if (ok) op[f * 4] = make_float4(p0, p1, p2, p3);
    }
}

extern "C" void kernel_launch(void* const* d_in, const int* in_sizes, int n_in,
                              void* d_out, int out_size) {
    const float* ja      = (const float*)d_in[0];
    const float* axes    = (const float*)d_in[1];
    const float* origins = (const float*)d_in[2];
    const float* mm      = (const float*)d_in[3];
    const float* mo      = (const float*)d_in[4];
    const int*   ctrl    = (const int*)d_in[5];
    const int*   msrc    = (const int*)d_in[6];
    const int*   mdst    = (const int*)d_in[7];
    const int*   types   = (const int*)d_in[8];
    float*       out     = (float*)d_out;

    const int Bn   = in_sizes[0] / NDOF;
    const int grid = (Bn + 31) / 32;          // 32 batches per block
    fk_kernel<<<grid, BLK>>>(ja, axes, origins, mm, mo, ctrl, msrc, mdst, types, out, Bn);
}